// round 1
// baseline (speedup 1.0000x reference)
#include <cuda_runtime.h>
#include <math.h>

#define D_MODEL 512
#define N_HEAD  8
#define D_QKV   64
#define BB      4
#define SS      2048
#define ROWS    (BB*SS)   // 8192

// Scratch (allocation-free rule: __device__ globals)
__device__ float g_qn [ROWS*D_MODEL];
__device__ float g_qh [ROWS*D_MODEL];
__device__ float g_kh [ROWS*D_MODEL];
__device__ float g_vh [ROWS*D_MODEL];
__device__ float g_att[ROWS*D_MODEL];

// ---------------------------------------------------------------------------
// LayerNorm: one warp per row of 512
// ---------------------------------------------------------------------------
__global__ void ln_kernel(const float* __restrict__ x,
                          const float* __restrict__ gamma,
                          const float* __restrict__ beta,
                          float* __restrict__ out) {
    int row  = blockIdx.x * 8 + (threadIdx.x >> 5);
    int lane = threadIdx.x & 31;
    const float4* xr = (const float4*)(x + (size_t)row * D_MODEL);
    float4 v[4];
    float s = 0.f;
#pragma unroll
    for (int i = 0; i < 4; i++) {
        v[i] = xr[lane + 32 * i];
        s += v[i].x + v[i].y + v[i].z + v[i].w;
    }
#pragma unroll
    for (int o = 16; o; o >>= 1) s += __shfl_xor_sync(0xffffffffu, s, o);
    float mu = s * (1.f / 512.f);
    float var = 0.f;
#pragma unroll
    for (int i = 0; i < 4; i++) {
        float a = v[i].x - mu, b = v[i].y - mu, c = v[i].z - mu, d = v[i].w - mu;
        var += a * a + b * b + c * c + d * d;
    }
#pragma unroll
    for (int o = 16; o; o >>= 1) var += __shfl_xor_sync(0xffffffffu, var, o);
    float rstd = rsqrtf(var * (1.f / 512.f) + 1e-6f);
    float4* orow = (float4*)(out + (size_t)row * D_MODEL);
    const float4* g4 = (const float4*)gamma;
    const float4* b4 = (const float4*)beta;
#pragma unroll
    for (int i = 0; i < 4; i++) {
        float4 g = g4[lane + 32 * i], bb = b4[lane + 32 * i];
        float4 o;
        o.x = (v[i].x - mu) * rstd * g.x + bb.x;
        o.y = (v[i].y - mu) * rstd * g.y + bb.y;
        o.z = (v[i].z - mu) * rstd * g.z + bb.z;
        o.w = (v[i].w - mu) * rstd * g.w + bb.w;
        orow[lane + 32 * i] = o;
    }
}

// ---------------------------------------------------------------------------
// SGEMM: C[M,512] = A[M,512] @ W[512,512] (+ residual). 64x64x16 tiles,
// 256 threads, 4x4 micro-tile per thread.
// ---------------------------------------------------------------------------
template <bool RES>
__global__ void gemm64_kernel(const float* __restrict__ A,
                              const float* __restrict__ W,
                              float* __restrict__ C,
                              const float* __restrict__ res) {
    const int K = 512, N = 512;
    __shared__ float As[16][64];  // [k][m]
    __shared__ float Ws[16][64];  // [k][n]
    int m0 = blockIdx.y * 64;
    int n0 = blockIdx.x * 64;
    int t = threadIdx.x;
    int tx = t & 15, ty = t >> 4;
    float acc[4][4] = {};
    for (int k0 = 0; k0 < K; k0 += 16) {
        {   // A tile 64x16 -> transposed store
            int row = t >> 2, c4 = t & 3;
            float4 v = *(const float4*)(A + (size_t)(m0 + row) * K + k0 + c4 * 4);
            As[c4 * 4 + 0][row] = v.x;
            As[c4 * 4 + 1][row] = v.y;
            As[c4 * 4 + 2][row] = v.z;
            As[c4 * 4 + 3][row] = v.w;
        }
        {   // W tile 16x64
            int row = t >> 4, c4 = t & 15;
            float4 v = *(const float4*)(W + (size_t)(k0 + row) * N + n0 + c4 * 4);
            *(float4*)&Ws[row][c4 * 4] = v;
        }
        __syncthreads();
#pragma unroll
        for (int kk = 0; kk < 16; kk++) {
            float4 a = *(float4*)&As[kk][ty * 4];
            float4 b = *(float4*)&Ws[kk][tx * 4];
            float av[4] = {a.x, a.y, a.z, a.w};
            float bv[4] = {b.x, b.y, b.z, b.w};
#pragma unroll
            for (int i = 0; i < 4; i++)
#pragma unroll
                for (int j = 0; j < 4; j++) acc[i][j] += av[i] * bv[j];
        }
        __syncthreads();
    }
#pragma unroll
    for (int i = 0; i < 4; i++) {
        int row = m0 + ty * 4 + i;
        float4 o = make_float4(acc[i][0], acc[i][1], acc[i][2], acc[i][3]);
        if (RES) {
            float4 r = *(const float4*)(res + (size_t)row * N + n0 + tx * 4);
            o.x += r.x; o.y += r.y; o.z += r.z; o.w += r.w;
        }
        *(float4*)(C + (size_t)row * N + n0 + tx * 4) = o;
    }
}

// ---------------------------------------------------------------------------
// Flash attention (fp32): per (b, h, 64-q-tile) CTA, loop 64-key tiles with
// online softmax. Q/K tiles stored transposed [d][row] in smem.
// ---------------------------------------------------------------------------
__global__ void attn_kernel(const float* __restrict__ qh,
                            const float* __restrict__ kh,
                            const float* __restrict__ vh,
                            const int* __restrict__ mask,
                            float* __restrict__ out) {
    extern __shared__ float sm[];
    float* qsT = sm;               // [64 d][64 row]
    float* ksT = qsT + 64 * 64;    // [64 d][64 row]
    float* vs  = ksT + 64 * 64;    // [64 k][64 oc]
    float* Ssm = vs + 64 * 64;     // [64 q][65]
    float* m_s = Ssm + 64 * 65;
    float* l_s = m_s + 64;
    float* alpha_s = l_s + 64;

    int q0 = blockIdx.x * 64;
    int h  = blockIdx.y;
    int b  = blockIdx.z;
    int t = threadIdx.x, tx = t & 15, ty = t >> 4;

    const float* qbase = qh + (size_t)b * SS * D_MODEL + h * D_QKV;
    const float* kbase = kh + (size_t)b * SS * D_MODEL + h * D_QKV;
    const float* vbase = vh + (size_t)b * SS * D_MODEL + h * D_QKV;
    const int*   mbase = mask + (size_t)b * SS * SS;

#pragma unroll
    for (int r = 0; r < 4; r++) {     // Q tile transposed load
        int idx4 = t + 256 * r;
        int row = idx4 >> 4, d4 = idx4 & 15;
        float4 v = *(const float4*)(qbase + (size_t)(q0 + row) * D_MODEL + d4 * 4);
        qsT[(d4 * 4 + 0) * 64 + row] = v.x;
        qsT[(d4 * 4 + 1) * 64 + row] = v.y;
        qsT[(d4 * 4 + 2) * 64 + row] = v.z;
        qsT[(d4 * 4 + 3) * 64 + row] = v.w;
    }
    if (t < 64) { m_s[t] = -1e30f; l_s[t] = 0.f; }

    float o_acc[4][4] = {};
    const float scale = 0.125f;  // 1/sqrt(64)

    for (int k0 = 0; k0 < SS; k0 += 64) {
        __syncthreads();
#pragma unroll
        for (int r = 0; r < 4; r++) {   // K transposed + V natural
            int idx4 = t + 256 * r;
            int row = idx4 >> 4, d4 = idx4 & 15;
            float4 v = *(const float4*)(kbase + (size_t)(k0 + row) * D_MODEL + d4 * 4);
            ksT[(d4 * 4 + 0) * 64 + row] = v.x;
            ksT[(d4 * 4 + 1) * 64 + row] = v.y;
            ksT[(d4 * 4 + 2) * 64 + row] = v.z;
            ksT[(d4 * 4 + 3) * 64 + row] = v.w;
            float4 w = *(const float4*)(vbase + (size_t)(k0 + row) * D_MODEL + d4 * 4);
            *(float4*)&vs[row * 64 + d4 * 4] = w;
        }
        __syncthreads();

        // scores S = (Q @ K^T) * scale, 4x4 per thread
        float sacc[4][4] = {};
#pragma unroll
        for (int d = 0; d < 64; d++) {
            float4 a = *(float4*)&qsT[d * 64 + ty * 4];
            float4 bq = *(float4*)&ksT[d * 64 + tx * 4];
            float av[4] = {a.x, a.y, a.z, a.w};
            float bv[4] = {bq.x, bq.y, bq.z, bq.w};
#pragma unroll
            for (int i = 0; i < 4; i++)
#pragma unroll
                for (int j = 0; j < 4; j++) sacc[i][j] += av[i] * bv[j];
        }
        // mask + store to smem
#pragma unroll
        for (int i = 0; i < 4; i++) {
            int qr = ty * 4 + i;
            const int4 mm = *(const int4*)(mbase + (size_t)(q0 + qr) * SS + k0 + tx * 4);
            Ssm[qr * 65 + tx * 4 + 0] = mm.x ? sacc[i][0] * scale : -1e9f;
            Ssm[qr * 65 + tx * 4 + 1] = mm.y ? sacc[i][1] * scale : -1e9f;
            Ssm[qr * 65 + tx * 4 + 2] = mm.z ? sacc[i][2] * scale : -1e9f;
            Ssm[qr * 65 + tx * 4 + 3] = mm.w ? sacc[i][3] * scale : -1e9f;
        }
        __syncthreads();

        // online softmax: one thread per q-row
        if (t < 64) {
            float mold = m_s[t];
            float mx = mold;
#pragma unroll 8
            for (int c = 0; c < 64; c++) mx = fmaxf(mx, Ssm[t * 65 + c]);
            float alpha = __expf(mold - mx);
            float sum = 0.f;
#pragma unroll 8
            for (int c = 0; c < 64; c++) {
                float p = __expf(Ssm[t * 65 + c] - mx);
                Ssm[t * 65 + c] = p;
                sum += p;
            }
            l_s[t] = l_s[t] * alpha + sum;
            m_s[t] = mx;
            alpha_s[t] = alpha;
        }
        __syncthreads();

        // O = O*alpha + P @ V
        float al[4];
#pragma unroll
        for (int i = 0; i < 4; i++) al[i] = alpha_s[ty * 4 + i];
#pragma unroll
        for (int i = 0; i < 4; i++)
#pragma unroll
            for (int j = 0; j < 4; j++) o_acc[i][j] *= al[i];
#pragma unroll
        for (int kk = 0; kk < 64; kk++) {
            float p[4];
#pragma unroll
            for (int i = 0; i < 4; i++) p[i] = Ssm[(ty * 4 + i) * 65 + kk];
            float4 vv = *(float4*)&vs[kk * 64 + tx * 4];
            float bv[4] = {vv.x, vv.y, vv.z, vv.w};
#pragma unroll
            for (int i = 0; i < 4; i++)
#pragma unroll
                for (int j = 0; j < 4; j++) o_acc[i][j] += p[i] * bv[j];
        }
    }
    __syncthreads();

    float linv[4];
#pragma unroll
    for (int i = 0; i < 4; i++) linv[i] = 1.f / l_s[ty * 4 + i];
#pragma unroll
    for (int i = 0; i < 4; i++) {
        int row = q0 + ty * 4 + i;
        float4 o = make_float4(o_acc[i][0] * linv[i], o_acc[i][1] * linv[i],
                               o_acc[i][2] * linv[i], o_acc[i][3] * linv[i]);
        *(float4*)(out + ((size_t)b * SS + row) * D_MODEL + h * D_QKV + tx * 4) = o;
    }
}

// ---------------------------------------------------------------------------
extern "C" void kernel_launch(void* const* d_in, const int* in_sizes, int n_in,
                              void* d_out, int out_size) {
    const float* q     = (const float*)d_in[0];
    const float* k     = (const float*)d_in[1];
    const float* v     = (const float*)d_in[2];
    const int*   mask  = (const int*)d_in[3];
    const float* Wq    = (const float*)d_in[4];
    const float* Wk    = (const float*)d_in[5];
    const float* Wv    = (const float*)d_in[6];
    const float* Wfc   = (const float*)d_in[7];
    const float* gamma = (const float*)d_in[8];
    const float* beta  = (const float*)d_in[9];
    float* out = (float*)d_out;

    float *qn, *qh, *kh, *vh, *att;
    cudaGetSymbolAddress((void**)&qn,  g_qn);
    cudaGetSymbolAddress((void**)&qh,  g_qh);
    cudaGetSymbolAddress((void**)&kh,  g_kh);
    cudaGetSymbolAddress((void**)&vh,  g_vh);
    cudaGetSymbolAddress((void**)&att, g_att);

    // LayerNorm(q)
    ln_kernel<<<ROWS / 8, 256>>>(q, gamma, beta, qn);

    // projections
    dim3 ggrid(D_MODEL / 64, ROWS / 64);
    gemm64_kernel<false><<<ggrid, 256>>>(qn, Wq, qh, nullptr);
    gemm64_kernel<false><<<ggrid, 256>>>(k,  Wk, kh, nullptr);
    gemm64_kernel<false><<<ggrid, 256>>>(v,  Wv, vh, nullptr);

    // flash attention
    size_t smem = (3 * 64 * 64 + 64 * 65 + 3 * 64) * sizeof(float);
    cudaFuncSetAttribute(attn_kernel, cudaFuncAttributeMaxDynamicSharedMemorySize,
                         (int)smem);
    attn_kernel<<<dim3(SS / 64, N_HEAD, BB), 256, smem>>>(qh, kh, vh, mask, att);

    // FC + residual
    gemm64_kernel<true><<<ggrid, 256>>>(att, Wfc, out, q);
}

// round 2
// speedup vs baseline: 3.3311x; 3.3311x over previous
#include <cuda_runtime.h>
#include <math.h>
#include <stdint.h>

#define D_MODEL 512
#define N_HEAD  8
#define D_QKV   64
#define BB      4
#define SS      2048
#define ROWS    (BB*SS)   // 8192

// Scratch (allocation-free rule: __device__ globals)
__device__ float g_qn [ROWS*D_MODEL];
__device__ float g_qh [ROWS*D_MODEL];
__device__ float g_kh [ROWS*D_MODEL];
__device__ float g_vh [ROWS*D_MODEL];
__device__ float g_att[ROWS*D_MODEL];

// ---------------------------------------------------------------------------
// tf32 helpers
// ---------------------------------------------------------------------------
__device__ __forceinline__ uint32_t f2tf(float f) {
    uint32_t r;
    asm("cvt.rna.tf32.f32 %0, %1;" : "=r"(r) : "f"(f));
    return r;
}

// D += A(16x8) * B(8x8), tf32 in / fp32 acc, A row-major, B col-major
__device__ __forceinline__ void mma8(float* c, const uint32_t* a, const uint32_t* b) {
    asm volatile(
        "mma.sync.aligned.m16n8k8.row.col.f32.tf32.tf32.f32 "
        "{%0,%1,%2,%3},{%4,%5,%6,%7},{%8,%9},{%0,%1,%2,%3};"
        : "+f"(c[0]), "+f"(c[1]), "+f"(c[2]), "+f"(c[3])
        : "r"(a[0]), "r"(a[1]), "r"(a[2]), "r"(a[3]), "r"(b[0]), "r"(b[1]));
}

// ---------------------------------------------------------------------------
// LayerNorm: one warp per row of 512
// ---------------------------------------------------------------------------
__global__ void ln_kernel(const float* __restrict__ x,
                          const float* __restrict__ gamma,
                          const float* __restrict__ beta,
                          float* __restrict__ out) {
    int row  = blockIdx.x * 8 + (threadIdx.x >> 5);
    int lane = threadIdx.x & 31;
    const float4* xr = (const float4*)(x + (size_t)row * D_MODEL);
    float4 v[4];
    float s = 0.f;
#pragma unroll
    for (int i = 0; i < 4; i++) {
        v[i] = xr[lane + 32 * i];
        s += v[i].x + v[i].y + v[i].z + v[i].w;
    }
#pragma unroll
    for (int o = 16; o; o >>= 1) s += __shfl_xor_sync(0xffffffffu, s, o);
    float mu = s * (1.f / 512.f);
    float var = 0.f;
#pragma unroll
    for (int i = 0; i < 4; i++) {
        float a = v[i].x - mu, b = v[i].y - mu, c = v[i].z - mu, d = v[i].w - mu;
        var += a * a + b * b + c * c + d * d;
    }
#pragma unroll
    for (int o = 16; o; o >>= 1) var += __shfl_xor_sync(0xffffffffu, var, o);
    float rstd = rsqrtf(var * (1.f / 512.f) + 1e-6f);
    float4* orow = (float4*)(out + (size_t)row * D_MODEL);
    const float4* g4 = (const float4*)gamma;
    const float4* b4 = (const float4*)beta;
#pragma unroll
    for (int i = 0; i < 4; i++) {
        float4 g = g4[lane + 32 * i], bb = b4[lane + 32 * i];
        float4 o;
        o.x = (v[i].x - mu) * rstd * g.x + bb.x;
        o.y = (v[i].y - mu) * rstd * g.y + bb.y;
        o.z = (v[i].z - mu) * rstd * g.z + bb.z;
        o.w = (v[i].w - mu) * rstd * g.w + bb.w;
        orow[lane + 32 * i] = o;
    }
}

// ---------------------------------------------------------------------------
// tf32 MMA GEMM: C[M,512] = A[M,512] @ W[512,512] (+ residual)
// Block: 256 thr (8 warps), tile 128(M) x 128(N), K-iter 32.
// Warp grid 4(m) x 2(n): warp tile 32x64 (2 m-tiles x 8 n-tiles of m16n8).
// ---------------------------------------------------------------------------
template <bool RES>
__global__ void __launch_bounds__(256) gemm_tf32(const float* __restrict__ A,
                                                 const float* __restrict__ W,
                                                 float* __restrict__ C,
                                                 const float* __restrict__ res) {
    __shared__ uint32_t As[128 * 40];   // [m][k] pitch 40
    __shared__ uint32_t Ws[32 * 132];   // [k][n] pitch 132
    const int m0 = blockIdx.y * 128, n0 = blockIdx.x * 128;
    const int t = threadIdx.x;
    const int warp = t >> 5, lane = t & 31, g = lane >> 2, tig = lane & 3;
    const int mw = warp >> 1, nw = warp & 1;

    float acc[2][8][4] = {};

    for (int k0 = 0; k0 < 512; k0 += 32) {
        __syncthreads();
        // stage A tile: 128 rows x 32 k
#pragma unroll
        for (int i = 0; i < 4; i++) {
            int idx = t + 256 * i;
            int row = idx >> 3, k4 = idx & 7;
            float4 v = *(const float4*)(A + (size_t)(m0 + row) * 512 + k0 + k4 * 4);
            uint32_t* p = &As[row * 40 + k4 * 4];
            p[0] = f2tf(v.x); p[1] = f2tf(v.y); p[2] = f2tf(v.z); p[3] = f2tf(v.w);
        }
        // stage W tile: 32 k x 128 n
#pragma unroll
        for (int i = 0; i < 4; i++) {
            int idx = t + 256 * i;
            int kk = idx >> 5, n4 = idx & 31;
            float4 v = *(const float4*)(W + (size_t)(k0 + kk) * 512 + n0 + n4 * 4);
            uint32_t* p = &Ws[kk * 132 + n4 * 4];
            p[0] = f2tf(v.x); p[1] = f2tf(v.y); p[2] = f2tf(v.z); p[3] = f2tf(v.w);
        }
        __syncthreads();
#pragma unroll
        for (int s = 0; s < 4; s++) {
            uint32_t a[2][4];
#pragma unroll
            for (int mt = 0; mt < 2; mt++) {
                int r = mw * 32 + mt * 16 + g;
                uint2 lo = *(const uint2*)&As[r * 40 + 8 * s + 2 * tig];
                uint2 hi = *(const uint2*)&As[(r + 8) * 40 + 8 * s + 2 * tig];
                a[mt][0] = lo.x; a[mt][2] = lo.y; a[mt][1] = hi.x; a[mt][3] = hi.y;
            }
#pragma unroll
            for (int nt = 0; nt < 8; nt++) {
                int col = nw * 64 + nt * 8 + g;
                uint32_t b[2];
                b[0] = Ws[(8 * s + 2 * tig)     * 132 + col];
                b[1] = Ws[(8 * s + 2 * tig + 1) * 132 + col];
                mma8(acc[0][nt], a[0], b);
                mma8(acc[1][nt], a[1], b);
            }
        }
    }
    // epilogue
#pragma unroll
    for (int mt = 0; mt < 2; mt++) {
        int rbase = m0 + mw * 32 + mt * 16 + g;
#pragma unroll
        for (int nt = 0; nt < 8; nt++) {
            int col = n0 + nw * 64 + nt * 8 + 2 * tig;
            float2 v0 = make_float2(acc[mt][nt][0], acc[mt][nt][1]);
            float2 v1 = make_float2(acc[mt][nt][2], acc[mt][nt][3]);
            if (RES) {
                float2 r0 = *(const float2*)(res + (size_t)rbase * 512 + col);
                float2 r1 = *(const float2*)(res + (size_t)(rbase + 8) * 512 + col);
                v0.x += r0.x; v0.y += r0.y; v1.x += r1.x; v1.y += r1.y;
            }
            *(float2*)(C + (size_t)rbase * 512 + col)       = v0;
            *(float2*)(C + (size_t)(rbase + 8) * 512 + col) = v1;
        }
    }
}

// ---------------------------------------------------------------------------
// Flash attention with tf32 MMA. 128 thr (4 warps). Each warp: 16 q-rows x
// all 64 k-cols per tile -> register-resident online softmax; P stays in
// registers (C-fragment reused as A-fragment via k-permutation trick).
// ---------------------------------------------------------------------------
__global__ void __launch_bounds__(128) attn_tf32(const float* __restrict__ qh,
                                                 const float* __restrict__ kh,
                                                 const float* __restrict__ vh,
                                                 const int* __restrict__ mask,
                                                 float* __restrict__ out) {
    __shared__ uint32_t Ks[64 * 72];   // [krow][d]   pitch 72 (LDS.64 conflict-free)
    __shared__ uint32_t Vs[64 * 68];   // [krow][dout] pitch 68 (LDS.32 conflict-free)

    const int q0 = blockIdx.x * 64;
    const int h  = blockIdx.y;
    const int b  = blockIdx.z;
    const int t = threadIdx.x, warp = t >> 5, lane = t & 31;
    const int g = lane >> 2, tig = lane & 3;

    const float* qbase = qh + (size_t)b * SS * D_MODEL + h * D_QKV;
    const float* kbase = kh + (size_t)b * SS * D_MODEL + h * D_QKV;
    const float* vbase = vh + (size_t)b * SS * D_MODEL + h * D_QKV;
    const int*   mbase = mask + (size_t)b * SS * SS;

    const int r0 = warp * 16 + g, r1 = r0 + 8;

    // Q fragments live in registers for the whole kernel.
    uint32_t qa[8][4];
#pragma unroll
    for (int s = 0; s < 8; s++) {
        float2 lo = *(const float2*)(qbase + (size_t)(q0 + r0) * D_MODEL + 8 * s + 2 * tig);
        float2 hi = *(const float2*)(qbase + (size_t)(q0 + r1) * D_MODEL + 8 * s + 2 * tig);
        qa[s][0] = f2tf(lo.x); qa[s][2] = f2tf(lo.y);
        qa[s][1] = f2tf(hi.x); qa[s][3] = f2tf(hi.y);
    }

    float o[8][4] = {};
    float mr0 = -1e30f, mr1 = -1e30f, l0 = 0.f, l1 = 0.f;

    for (int k0 = 0; k0 < SS; k0 += 64) {
        __syncthreads();
        // stage K, V tiles (64 rows x 64 d), tf32-converted
#pragma unroll
        for (int i = 0; i < 8; i++) {
            int idx = t + 128 * i;
            int row = idx >> 4, d4 = idx & 15;
            float4 kv = *(const float4*)(kbase + (size_t)(k0 + row) * D_MODEL + d4 * 4);
            uint32_t* pk = &Ks[row * 72 + d4 * 4];
            pk[0] = f2tf(kv.x); pk[1] = f2tf(kv.y); pk[2] = f2tf(kv.z); pk[3] = f2tf(kv.w);
            float4 vv = *(const float4*)(vbase + (size_t)(k0 + row) * D_MODEL + d4 * 4);
            uint32_t* pv = &Vs[row * 68 + d4 * 4];
            pv[0] = f2tf(vv.x); pv[1] = f2tf(vv.y); pv[2] = f2tf(vv.z); pv[3] = f2tf(vv.w);
        }
        // prefetch mask int2 pairs for this tile
        int2 mk0[8], mk1[8];
#pragma unroll
        for (int nt = 0; nt < 8; nt++) {
            mk0[nt] = *(const int2*)(mbase + (size_t)(q0 + r0) * SS + k0 + nt * 8 + 2 * tig);
            mk1[nt] = *(const int2*)(mbase + (size_t)(q0 + r1) * SS + k0 + nt * 8 + 2 * tig);
        }
        __syncthreads();

        // S = Q @ K^T  (per warp: 16 x 64)
        float sc[8][4] = {};
#pragma unroll
        for (int s = 0; s < 8; s++) {
#pragma unroll
            for (int nt = 0; nt < 8; nt++) {
                uint2 kk = *(const uint2*)&Ks[(nt * 8 + g) * 72 + 8 * s + 2 * tig];
                uint32_t bfr[2] = {kk.x, kk.y};
                mma8(sc[nt], qa[s], bfr);
            }
        }

        // mask + scale + online softmax (register-resident)
        const float inv8 = 0.125f;   // 1/sqrt(64)
        float mx0 = mr0, mx1 = mr1;
#pragma unroll
        for (int nt = 0; nt < 8; nt++) {
            sc[nt][0] = mk0[nt].x ? sc[nt][0] * inv8 : -1e9f;
            sc[nt][1] = mk0[nt].y ? sc[nt][1] * inv8 : -1e9f;
            sc[nt][2] = mk1[nt].x ? sc[nt][2] * inv8 : -1e9f;
            sc[nt][3] = mk1[nt].y ? sc[nt][3] * inv8 : -1e9f;
            mx0 = fmaxf(mx0, fmaxf(sc[nt][0], sc[nt][1]));
            mx1 = fmaxf(mx1, fmaxf(sc[nt][2], sc[nt][3]));
        }
        mx0 = fmaxf(mx0, __shfl_xor_sync(0xffffffffu, mx0, 1));
        mx0 = fmaxf(mx0, __shfl_xor_sync(0xffffffffu, mx0, 2));
        mx1 = fmaxf(mx1, __shfl_xor_sync(0xffffffffu, mx1, 1));
        mx1 = fmaxf(mx1, __shfl_xor_sync(0xffffffffu, mx1, 2));

        float a0 = __expf(mr0 - mx0), a1 = __expf(mr1 - mx1);
        mr0 = mx0; mr1 = mx1;

        float s0 = 0.f, s1 = 0.f;
#pragma unroll
        for (int nt = 0; nt < 8; nt++) {
            float p;
            p = __uint_as_float(f2tf(__expf(sc[nt][0] - mx0))); sc[nt][0] = p; s0 += p;
            p = __uint_as_float(f2tf(__expf(sc[nt][1] - mx0))); sc[nt][1] = p; s0 += p;
            p = __uint_as_float(f2tf(__expf(sc[nt][2] - mx1))); sc[nt][2] = p; s1 += p;
            p = __uint_as_float(f2tf(__expf(sc[nt][3] - mx1))); sc[nt][3] = p; s1 += p;
        }
        s0 += __shfl_xor_sync(0xffffffffu, s0, 1);
        s0 += __shfl_xor_sync(0xffffffffu, s0, 2);
        s1 += __shfl_xor_sync(0xffffffffu, s1, 1);
        s1 += __shfl_xor_sync(0xffffffffu, s1, 2);
        l0 = l0 * a0 + s0;
        l1 = l1 * a1 + s1;

#pragma unroll
        for (int nt = 0; nt < 8; nt++) {
            o[nt][0] *= a0; o[nt][1] *= a0; o[nt][2] *= a1; o[nt][3] *= a1;
        }

        // O += P @ V : P C-fragments feed A-fragments directly (k permuted),
        // V read with the matching k-permutation (adjacent krow pairs).
#pragma unroll
        for (int sp = 0; sp < 8; sp++) {
            uint32_t pa[4] = {__float_as_uint(sc[sp][0]), __float_as_uint(sc[sp][2]),
                              __float_as_uint(sc[sp][1]), __float_as_uint(sc[sp][3])};
#pragma unroll
            for (int nt = 0; nt < 8; nt++) {
                uint32_t bfr[2];
                bfr[0] = Vs[(8 * sp + 2 * tig)     * 68 + nt * 8 + g];
                bfr[1] = Vs[(8 * sp + 2 * tig + 1) * 68 + nt * 8 + g];
                mma8(o[nt], pa, bfr);
            }
        }
    }

    float il0 = 1.f / l0, il1 = 1.f / l1;
#pragma unroll
    for (int nt = 0; nt < 8; nt++) {
        int col = h * D_QKV + nt * 8 + 2 * tig;
        float2 v0 = make_float2(o[nt][0] * il0, o[nt][1] * il0);
        float2 v1 = make_float2(o[nt][2] * il1, o[nt][3] * il1);
        *(float2*)(out + ((size_t)b * SS + q0 + r0) * D_MODEL + col) = v0;
        *(float2*)(out + ((size_t)b * SS + q0 + r1) * D_MODEL + col) = v1;
    }
}

// ---------------------------------------------------------------------------
extern "C" void kernel_launch(void* const* d_in, const int* in_sizes, int n_in,
                              void* d_out, int out_size) {
    const float* q     = (const float*)d_in[0];
    const float* k     = (const float*)d_in[1];
    const float* v     = (const float*)d_in[2];
    const int*   mask  = (const int*)d_in[3];
    const float* Wq    = (const float*)d_in[4];
    const float* Wk    = (const float*)d_in[5];
    const float* Wv    = (const float*)d_in[6];
    const float* Wfc   = (const float*)d_in[7];
    const float* gamma = (const float*)d_in[8];
    const float* beta  = (const float*)d_in[9];
    float* out = (float*)d_out;

    float *qn, *qh, *kh, *vh, *att;
    cudaGetSymbolAddress((void**)&qn,  g_qn);
    cudaGetSymbolAddress((void**)&qh,  g_qh);
    cudaGetSymbolAddress((void**)&kh,  g_kh);
    cudaGetSymbolAddress((void**)&vh,  g_vh);
    cudaGetSymbolAddress((void**)&att, g_att);

    // LayerNorm(q)
    ln_kernel<<<ROWS / 8, 256>>>(q, gamma, beta, qn);

    // projections (tf32 MMA)
    dim3 ggrid(D_MODEL / 128, ROWS / 128);
    gemm_tf32<false><<<ggrid, 256>>>(qn, Wq, qh, nullptr);
    gemm_tf32<false><<<ggrid, 256>>>(k,  Wk, kh, nullptr);
    gemm_tf32<false><<<ggrid, 256>>>(v,  Wv, vh, nullptr);

    // flash attention (tf32 MMA)
    attn_tf32<<<dim3(SS / 64, N_HEAD, BB), 128>>>(qh, kh, vh, mask, att);

    // FC + residual
    gemm_tf32<true><<<ggrid, 256>>>(att, Wfc, out, q);
}